// round 1
// baseline (speedup 1.0000x reference)
#include <cuda_runtime.h>
#include <cuda_bf16.h>
#include <math.h>

// ---------------- Problem constants ----------------
#define BATCH   128
#define CIN     256
#define HIN     8
#define WIN     32
#define RH      16
#define RW      64
#define HF      8      // pooled H
#define WF      32     // pooled W
#define LPOS    256    // HF*WF
#define XOH     32
#define YOH     8
#define CENC    296    // 256 + 32 + 8
#define HID     256
#define NC      163
#define TLEN    32

#define PADH    18     // RH + 2
#define PADW    66     // RW + 2
#define PADHW   (PADH*PADW)   // 1188

// ---------------- Scratch (device globals; no allocation) ----------------
__device__ float g_res[BATCH*CIN*PADHW];          // padded resized input  (~156MB)
__device__ float g_enc[BATCH*LPOS*CENC];          // encoder features      (~39MB)
__device__ float g_pre[BATCH*LPOS*HID];           // enc @ We^T + attn_b   (~34MB)
__device__ float g_we [TLEN*BATCH*HID];           // word embeddings per step (4MB)
__device__ int   g_tok[TLEN*BATCH];
__device__ float g_hidden[BATCH*HID];
__device__ float g_hproj [BATCH*HID];
__device__ float g_rin   [BATCH*(HID+CENC)];      // [we(256) | ctx(296)] = 552
__device__ float g_gi    [BATCH*3*HID];
__device__ float g_gh    [BATCH*3*HID];
__device__ float g_nll   [TLEN*BATCH];

// ---------------- helpers ----------------
__device__ __forceinline__ float tanh_fast(float x){
    float y; asm("tanh.approx.f32 %0, %1;" : "=f"(y) : "f"(x)); return y;
}
__device__ __forceinline__ float warp_sum(float v){
    #pragma unroll
    for (int o = 16; o; o >>= 1) v += __shfl_down_sync(0xffffffffu, v, o);
    return v;
}

// ---------------- K0: bilinear 2x resize into zero-padded buffer ----------------
__global__ void resize_kernel(const float* __restrict__ x){
    int idx = blockIdx.x * 256 + threadIdx.x;
    if (idx >= BATCH*CIN*PADHW) return;
    int xp = idx % PADW;
    int t  = idx / PADW;
    int yp = t % PADH;  t /= PADH;
    int c  = t % CIN;
    int b  = t / CIN;
    float v = 0.f;
    if (xp >= 1 && xp < PADW-1 && yp >= 1 && yp < PADH-1){
        int yo = yp - 1, xo = xp - 1;       // 0..15, 0..63
        float sy = 0.5f*yo - 0.25f;
        int y0 = (int)floorf(sy); float fy = sy - (float)y0;
        int y0c = y0 < 0 ? 0 : y0;
        int y1c = (y0+1) > (HIN-1) ? (HIN-1) : (y0+1);
        float sx = 0.5f*xo - 0.25f;
        int x0 = (int)floorf(sx); float fx = sx - (float)x0;
        int x0c = x0 < 0 ? 0 : x0;
        int x1c = (x0+1) > (WIN-1) ? (WIN-1) : (x0+1);
        const float* base = x + (size_t)(b*CIN + c) * (HIN*WIN);
        float v00 = base[y0c*WIN + x0c], v01 = base[y0c*WIN + x1c];
        float v10 = base[y1c*WIN + x0c], v11 = base[y1c*WIN + x1c];
        v = (1.f-fy)*((1.f-fx)*v00 + fx*v01) + fy*((1.f-fx)*v10 + fx*v11);
    }
    g_res[idx] = v;
}

// ---------------- K1: conv3x3 + bias + relu + maxpool2 -> enc[:, :, 0:256] ----------------
// grid (BATCH, 32 och-groups), 128 threads. Each thread: 2 adjacent pooled pixels x 8 och.
__global__ __launch_bounds__(128) void conv_pool_kernel(const float* __restrict__ conv_w,
                                                        const float* __restrict__ conv_b){
    __shared__ float tile[PADHW];
    __shared__ float wsm[72];
    int b    = blockIdx.x;
    int och0 = blockIdx.y * 8;
    int tid  = threadIdx.x;
    int py   = tid >> 4;            // 0..7
    int px0  = (tid & 15) << 1;     // 0,2,..,30
    int py2  = py << 1;
    int px2  = px0 << 1;
    float acc[8][8];
    #pragma unroll
    for (int o = 0; o < 8; o++)
        #pragma unroll
        for (int p = 0; p < 8; p++) acc[o][p] = 0.f;

    const float* src = g_res + (size_t)b * CIN * PADHW;
    for (int c = 0; c < CIN; c++){
        __syncthreads();
        #pragma unroll
        for (int e = tid; e < PADHW; e += 128) tile[e] = src[c*PADHW + e];
        if (tid < 72) wsm[tid] = conv_w[(och0 + tid/9)*2304 + c*9 + (tid%9)];
        __syncthreads();

        float inr[4][6];
        #pragma unroll
        for (int rr = 0; rr < 4; rr++)
            #pragma unroll
            for (int cc = 0; cc < 6; cc++)
                inr[rr][cc] = tile[(py2+rr)*PADW + px2 + cc];

        #pragma unroll
        for (int o = 0; o < 8; o++){
            float w0=wsm[o*9+0], w1=wsm[o*9+1], w2=wsm[o*9+2];
            float w3=wsm[o*9+3], w4=wsm[o*9+4], w5=wsm[o*9+5];
            float w6=wsm[o*9+6], w7=wsm[o*9+7], w8=wsm[o*9+8];
            #pragma unroll
            for (int r = 0; r < 2; r++)
                #pragma unroll
                for (int q = 0; q < 4; q++){
                    float s = acc[o][r*4+q];
                    s += inr[r  ][q  ]*w0 + inr[r  ][q+1]*w1 + inr[r  ][q+2]*w2;
                    s += inr[r+1][q  ]*w3 + inr[r+1][q+1]*w4 + inr[r+1][q+2]*w5;
                    s += inr[r+2][q  ]*w6 + inr[r+2][q+1]*w7 + inr[r+2][q+2]*w8;
                    acc[o][r*4+q] = s;
                }
        }
    }
    int l0 = py*WF + px0;
    #pragma unroll
    for (int o = 0; o < 8; o++){
        float bias = conv_b[och0+o];
        float m0 = fmaxf(fmaxf(acc[o][0],acc[o][1]), fmaxf(acc[o][4],acc[o][5]));
        float m1 = fmaxf(fmaxf(acc[o][2],acc[o][3]), fmaxf(acc[o][6],acc[o][7]));
        g_enc[((size_t)b*LPOS + l0    )*CENC + och0 + o] = fmaxf(m0 + bias, 0.f);
        g_enc[((size_t)b*LPOS + l0 + 1)*CENC + och0 + o] = fmaxf(m1 + bias, 0.f);
    }
}

// ---------------- K2: positional channels enc[:, :, 256:296] ----------------
__global__ void pos_kernel(const float* __restrict__ x_emb, const float* __restrict__ y_emb){
    int idx = blockIdx.x * 256 + threadIdx.x;
    if (idx >= BATCH*LPOS*40) return;
    int c40 = idx % 40;
    int l   = (idx / 40) % LPOS;
    int b   = idx / (40*LPOS);
    int y = l / WF, xx = l % WF;
    float v = (c40 < 32) ? x_emb[xx*XOH + c40] : y_emb[y*YOH + (c40-32)];
    g_enc[((size_t)b*LPOS + l)*CENC + 256 + c40] = v;
}

// ---------------- token gather indices ----------------
__global__ void tok_kernel(const int* __restrict__ dec_t){
    int idx = blockIdx.x*256 + threadIdx.x;
    if (idx >= TLEN*BATCH) return;
    int t = idx >> 7, b = idx & 127;
    g_tok[idx] = (t == 0) ? 0 : dec_t[b*TLEN + (t-1)];
}

// ---------------- generic TN GEMM: C[m,n] = sum_k A[row(m),k]*B[n,k] + bias[n] ----------------
#define BM 64
#define BN 64
#define BK 16
__global__ __launch_bounds__(256) void gemm_tn(const float* __restrict__ A, int lda,
                                               const int* __restrict__ gather,
                                               const float* __restrict__ B, int ldb,
                                               const float* __restrict__ bias,
                                               float* __restrict__ C, int ldc,
                                               int M, int N, int K){
    __shared__ __align__(16) float As[BK*68];
    __shared__ __align__(16) float Bs[BK*68];
    int m0 = blockIdx.x * BM, n0 = blockIdx.y * BN;
    int tid = threadIdx.x;
    int ty = tid >> 4, tx = tid & 15;
    float acc[4][4];
    #pragma unroll
    for (int i=0;i<4;i++) { acc[i][0]=0.f; acc[i][1]=0.f; acc[i][2]=0.f; acc[i][3]=0.f; }

    for (int k0 = 0; k0 < K; k0 += BK){
        #pragma unroll
        for (int e = tid; e < BM*BK; e += 256){
            int ml = e >> 4, kk = e & 15;
            int m = m0 + ml, k = k0 + kk;
            float v = 0.f;
            if (m < M && k < K){
                int row = gather ? gather[m] : m;
                v = A[(size_t)row*lda + k];
            }
            As[kk*68 + ml] = v;
        }
        #pragma unroll
        for (int e = tid; e < BN*BK; e += 256){
            int nl = e >> 4, kk = e & 15;
            int n = n0 + nl, k = k0 + kk;
            float v = 0.f;
            if (n < N && k < K) v = B[(size_t)n*ldb + k];
            Bs[kk*68 + nl] = v;
        }
        __syncthreads();
        #pragma unroll
        for (int kk = 0; kk < BK; kk++){
            float4 a = *(const float4*)&As[kk*68 + ty*4];
            float4 bb = *(const float4*)&Bs[kk*68 + tx*4];
            float av[4] = {a.x, a.y, a.z, a.w};
            float bv[4] = {bb.x, bb.y, bb.z, bb.w};
            #pragma unroll
            for (int i=0;i<4;i++)
                #pragma unroll
                for (int j=0;j<4;j++) acc[i][j] += av[i]*bv[j];
        }
        __syncthreads();
    }
    #pragma unroll
    for (int i=0;i<4;i++){
        int m = m0 + ty*4 + i;
        if (m >= M) continue;
        #pragma unroll
        for (int j=0;j<4;j++){
            int n = n0 + tx*4 + j;
            if (n >= N) continue;
            float bi = bias ? bias[n] : 0.f;
            C[(size_t)m*ldc + n] = acc[i][j] + bi;
        }
    }
}

// ---------------- zero hidden ----------------
__global__ void zero_hidden_kernel(){
    int idx = blockIdx.x*256 + threadIdx.x;
    if (idx < BATCH*HID) g_hidden[idx] = 0.f;
}

// ---------------- attention (scores -> softmax -> ctx) ; also copies we into rin ----------------
__global__ __launch_bounds__(256) void attn_kernel(const float* __restrict__ attn_v_p, int t){
    int b = blockIdx.x, tid = threadIdx.x;
    __shared__ float hp[HID], vv[HID], sc[LPOS], red[256];
    hp[tid] = g_hproj[b*HID + tid];
    vv[tid] = attn_v_p[tid];
    g_rin[b*552 + tid] = g_we[((size_t)t*BATCH + b)*HID + tid];
    __syncthreads();
    int warp = tid >> 5, lane = tid & 31;
    for (int l = warp; l < LPOS; l += 8){
        const float* p = g_pre + ((size_t)b*LPOS + l)*HID;
        float s = 0.f;
        #pragma unroll
        for (int i = 0; i < 8; i++){
            int h = lane + 32*i;
            s += vv[h] * tanh_fast(p[h] + hp[h]);
        }
        s = warp_sum(s);
        if (lane == 0) sc[l] = s;
    }
    __syncthreads();
    red[tid] = sc[tid]; __syncthreads();
    for (int s = 128; s; s >>= 1){ if (tid < s) red[tid] = fmaxf(red[tid], red[tid+s]); __syncthreads(); }
    float mx = red[0]; __syncthreads();
    float e = __expf(sc[tid] - mx);
    red[tid] = e; __syncthreads();
    for (int s = 128; s; s >>= 1){ if (tid < s) red[tid] += red[tid+s]; __syncthreads(); }
    float inv = 1.f / red[0];
    __syncthreads();
    sc[tid] = e * inv;
    __syncthreads();
    const float* eb = g_enc + (size_t)b*LPOS*CENC;
    for (int c = tid; c < CENC; c += 256){
        float acc = 0.f;
        #pragma unroll 8
        for (int l = 0; l < LPOS; l++) acc += sc[l] * eb[l*CENC + c];
        g_rin[b*552 + 256 + c] = acc;
    }
}

// ---------------- GRU gates: h = (1-z)*n + z*h ----------------
__global__ void gates_kernel(){
    int idx = blockIdx.x*256 + threadIdx.x;
    if (idx >= BATCH*HID) return;
    int b = idx >> 8, h = idx & 255;
    const float* gi = g_gi + b*768;
    const float* gh = g_gh + b*768;
    float r = 1.f/(1.f + __expf(-(gi[h]     + gh[h])));
    float z = 1.f/(1.f + __expf(-(gi[256+h] + gh[256+h])));
    float n = tanhf(gi[512+h] + r*gh[512+h]);
    float hp = g_hidden[idx];
    g_hidden[idx] = (1.f - z)*n + z*hp;
}

// ---------------- output head: logits + log_softmax + NLL ----------------
__global__ __launch_bounds__(256) void logits_kernel(const float* __restrict__ out_w,
                                                     const float* __restrict__ out_b,
                                                     const int* __restrict__ word_t, int t){
    int b = blockIdx.x, tid = threadIdx.x;
    __shared__ __align__(16) float hs[HID];
    __shared__ float lg[NC];
    __shared__ float red[256];
    hs[tid] = g_hidden[b*HID + tid];
    __syncthreads();
    float logit = -1e30f;
    if (tid < NC){
        const float4* w4 = (const float4*)(out_w + (size_t)tid*HID);
        const float4* h4 = (const float4*)hs;
        float a0=0.f, a1=0.f, a2=0.f, a3=0.f;
        #pragma unroll
        for (int k = 0; k < HID/4; k++){
            float4 w = w4[k]; float4 h = h4[k];
            a0 += w.x*h.x; a1 += w.y*h.y; a2 += w.z*h.z; a3 += w.w*h.w;
        }
        logit = (a0+a1) + (a2+a3) + out_b[tid];
        lg[tid] = logit;
    }
    red[tid] = logit; __syncthreads();
    for (int s = 128; s; s >>= 1){ if (tid < s) red[tid] = fmaxf(red[tid], red[tid+s]); __syncthreads(); }
    float mx = red[0]; __syncthreads();
    red[tid] = (tid < NC) ? __expf(lg[tid] - mx) : 0.f; __syncthreads();
    for (int s = 128; s; s >>= 1){ if (tid < s) red[tid] += red[tid+s]; __syncthreads(); }
    if (tid == 0){
        float lse = mx + logf(red[0]);
        int tgt = word_t[b*TLEN + t];
        float v = 0.f;
        if (tgt >= 0){
            int tc = tgt > (NC-1) ? (NC-1) : tgt;
            v = lse - lg[tc];
        }
        g_nll[t*BATCH + b] = v;
    }
}

// ---------------- final reduce: loss = 0.2 * sum(nll)/B ----------------
__global__ void reduce_kernel(float* __restrict__ out){
    __shared__ float red[256];
    int tid = threadIdx.x;
    float s = 0.f;
    for (int i = tid; i < TLEN*BATCH; i += 256) s += g_nll[i];
    red[tid] = s; __syncthreads();
    for (int k = 128; k; k >>= 1){ if (tid < k) red[tid] += red[tid+k]; __syncthreads(); }
    if (tid == 0) out[0] = 0.2f * red[0] / (float)BATCH;
}

// ---------------- host ----------------
extern "C" void kernel_launch(void* const* d_in, const int* in_sizes, int n_in,
                              void* d_out, int out_size){
    const float* x        = (const float*)d_in[0];
    const int*   dec_t    = (const int*)  d_in[1];
    const int*   word_t   = (const int*)  d_in[2];
    const float* conv_w   = (const float*)d_in[3];
    const float* conv_b   = (const float*)d_in[4];
    const float* emb_dec  = (const float*)d_in[5];
    const float* word_w   = (const float*)d_in[6];
    const float* word_b   = (const float*)d_in[7];
    const float* attn_w   = (const float*)d_in[8];
    const float* attn_b   = (const float*)d_in[9];
    const float* attn_v   = (const float*)d_in[10];
    const float* gru_wih  = (const float*)d_in[11];
    const float* gru_bih  = (const float*)d_in[12];
    const float* gru_whh  = (const float*)d_in[13];
    const float* gru_bhh  = (const float*)d_in[14];
    const float* out_w    = (const float*)d_in[15];
    const float* out_b    = (const float*)d_in[16];
    const float* x_emb    = (const float*)d_in[17];
    const float* y_emb    = (const float*)d_in[18];
    float* out = (float*)d_out;

    // device-global scratch addresses (kernels reference symbols directly)
    float *p_rin = nullptr, *p_hid = nullptr, *p_hpj = nullptr, *p_gi = nullptr, *p_gh = nullptr;
    float *p_enc = nullptr, *p_pre = nullptr, *p_we = nullptr;
    int   *p_tok = nullptr;
    cudaGetSymbolAddress((void**)&p_rin, g_rin);
    cudaGetSymbolAddress((void**)&p_hid, g_hidden);
    cudaGetSymbolAddress((void**)&p_hpj, g_hproj);
    cudaGetSymbolAddress((void**)&p_gi,  g_gi);
    cudaGetSymbolAddress((void**)&p_gh,  g_gh);
    cudaGetSymbolAddress((void**)&p_enc, g_enc);
    cudaGetSymbolAddress((void**)&p_pre, g_pre);
    cudaGetSymbolAddress((void**)&p_we,  g_we);
    cudaGetSymbolAddress((void**)&p_tok, g_tok);

    // 1) resize into padded buffer
    {
        int n = BATCH*CIN*PADHW;
        resize_kernel<<<(n + 255)/256, 256>>>(x);
    }
    // 2) conv + pool + relu -> enc channels [0,256)
    conv_pool_kernel<<<dim3(BATCH, 32), 128>>>(conv_w, conv_b);
    // 3) positional channels
    {
        int n = BATCH*LPOS*40;
        pos_kernel<<<(n + 255)/256, 256>>>(x_emb, y_emb);
    }
    // 4) teacher-forcing token indices + batched word embedding GEMM
    tok_kernel<<<(TLEN*BATCH + 255)/256, 256>>>(dec_t);
    gemm_tn<<<dim3((TLEN*BATCH)/BM, HID/BN), 256>>>(
        emb_dec, NC, p_tok, word_w, NC, word_b, p_we, HID, TLEN*BATCH, HID, NC);
    // 5) enc pre-projection: pre = enc @ We^T + attn_b   (We = attn_w[:,256:552])
    gemm_tn<<<dim3((BATCH*LPOS)/BM, HID/BN), 256>>>(
        p_enc, CENC, nullptr, attn_w + 256, 2*HID + XOH + YOH, attn_b,
        p_pre, HID, BATCH*LPOS, HID, CENC);
    // 6) init hidden
    zero_hidden_kernel<<<(BATCH*HID + 255)/256, 256>>>();

    // 7) sequential decoder
    for (int t = 0; t < TLEN; t++){
        // hproj = hidden @ Wh^T  (Wh = attn_w[:,0:256]), no bias (attn_b already in pre)
        gemm_tn<<<dim3(BATCH/BM, HID/BN), 256>>>(
            p_hid, HID, nullptr, attn_w, 2*HID + XOH + YOH, nullptr,
            p_hpj, HID, BATCH, HID, HID);
        // attention: scores/softmax/ctx, assemble rin = [we_t | ctx]
        attn_kernel<<<BATCH, 256>>>(attn_v, t);
        // gi = rin @ wih^T + bih ; gh = hidden @ whh^T + bhh
        gemm_tn<<<dim3(BATCH/BM, (3*HID)/BN), 256>>>(
            p_rin, 552, nullptr, gru_wih, 552, gru_bih, p_gi, 3*HID, BATCH, 3*HID, 552);
        gemm_tn<<<dim3(BATCH/BM, (3*HID)/BN), 256>>>(
            p_hid, HID, nullptr, gru_whh, HID, gru_bhh, p_gh, 3*HID, BATCH, 3*HID, HID);
        // gates -> hidden (in place)
        gates_kernel<<<(BATCH*HID + 255)/256, 256>>>();
        // logits + log_softmax + nll
        logits_kernel<<<BATCH, 256>>>(out_w, out_b, word_t, t);
    }
    // 8) loss
    reduce_kernel<<<1, 256>>>(out);
    (void)in_sizes; (void)n_in; (void)out_size;
}

// round 2
// speedup vs baseline: 1.3950x; 1.3950x over previous
#include <cuda_runtime.h>
#include <cuda_bf16.h>
#include <math.h>

// ---------------- Problem constants ----------------
#define BATCH   128
#define CIN     256
#define HIN     8
#define WIN     32
#define RH      16
#define RW      64
#define HF      8
#define WF      32
#define LPOS    256
#define XOH     32
#define YOH     8
#define CENC    296
#define HID     256
#define NC      163
#define TLEN    32

#define PADH    18
#define PADW    66

// ---------------- Scratch ----------------
__device__ float g_resT[BATCH*PADH*PADW*CIN];     // channel-last padded resized input
__device__ float g_wr  [9*CIN*CIN];               // weights [shift][cin][och]
__device__ float g_enc[BATCH*LPOS*CENC];
__device__ float g_pre[BATCH*LPOS*HID];
__device__ float g_we [TLEN*BATCH*HID];
__device__ int   g_tok[TLEN*BATCH];
__device__ float g_hidden[BATCH*HID];
__device__ float g_hproj [BATCH*HID];
__device__ float g_rin   [BATCH*(HID+CENC)];
__device__ float g_gi    [BATCH*3*HID];
__device__ float g_gh    [BATCH*3*HID];
__device__ float g_nll   [TLEN*BATCH];

// ---------------- helpers ----------------
__device__ __forceinline__ float tanh_fast(float x){
    float y; asm("tanh.approx.f32 %0, %1;" : "=f"(y) : "f"(x)); return y;
}
__device__ __forceinline__ float warp_sum(float v){
    #pragma unroll
    for (int o = 16; o; o >>= 1) v += __shfl_down_sync(0xffffffffu, v, o);
    return v;
}
__device__ __forceinline__ float tf32r(float f){
    unsigned u; asm("cvt.rna.tf32.f32 %0, %1;" : "=r"(u) : "f"(f));
    return __uint_as_float(u);
}
__device__ __forceinline__ void mma_tf32(float* c, const unsigned* a, unsigned b0, unsigned b1){
    asm volatile("mma.sync.aligned.m16n8k8.row.col.f32.tf32.tf32.f32 "
        "{%0,%1,%2,%3}, {%4,%5,%6,%7}, {%8,%9}, {%0,%1,%2,%3};"
        : "+f"(c[0]), "+f"(c[1]), "+f"(c[2]), "+f"(c[3])
        : "r"(a[0]), "r"(a[1]), "r"(a[2]), "r"(a[3]), "r"(b0), "r"(b1));
}

// ---------------- K0: bilinear 2x resize -> channel-last padded ----------------
__global__ void resize_cl_kernel(const float* __restrict__ x){
    int idx = blockIdx.x * 256 + threadIdx.x;
    if (idx >= BATCH*PADH*PADW*CIN) return;
    int c  = idx & 255;
    int t  = idx >> 8;
    int xp = t % PADW;  t /= PADW;
    int yp = t % PADH;
    int b  = t / PADH;
    float v = 0.f;
    if (xp >= 1 && xp < PADW-1 && yp >= 1 && yp < PADH-1){
        int yo = yp - 1, xo = xp - 1;
        float sy = 0.5f*yo - 0.25f;
        int y0 = (int)floorf(sy); float fy = sy - (float)y0;
        int y0c = y0 < 0 ? 0 : y0;
        int y1c = (y0+1) > (HIN-1) ? (HIN-1) : (y0+1);
        float sx = 0.5f*xo - 0.25f;
        int x0 = (int)floorf(sx); float fx = sx - (float)x0;
        int x0c = x0 < 0 ? 0 : x0;
        int x1c = (x0+1) > (WIN-1) ? (WIN-1) : (x0+1);
        const float* base = x + (size_t)(b*CIN + c) * (HIN*WIN);
        float v00 = base[y0c*WIN + x0c], v01 = base[y0c*WIN + x1c];
        float v10 = base[y1c*WIN + x0c], v11 = base[y1c*WIN + x1c];
        v = (1.f-fy)*((1.f-fx)*v00 + fx*v01) + fy*((1.f-fx)*v10 + fx*v11);
    }
    g_resT[idx] = v;
}

// ---------------- K0b: weight reorg [o][c][3][3] -> [s][c][o] ----------------
__global__ void wreorg_kernel(const float* __restrict__ conv_w){
    int idx = blockIdx.x*256 + threadIdx.x;
    if (idx >= 9*CIN*CIN) return;
    int o = idx & 255;
    int c = (idx >> 8) & 255;
    int s = idx >> 16;
    g_wr[idx] = conv_w[(o*CIN + c)*9 + s];
}

// ---------------- K1: conv3x3 as 9-shift tf32 tensor-core GEMM + pool + relu ----------------
// grid (BATCH, 8 ytiles), 512 threads (16 warps: 4 m-warps x 4 n-groups)
// block tile: M=128 (2 pre-pool rows x 64 x), N=256 och, K: 16 chunks of 16c x 9 shifts
#define CK 16           // channels per chunk
#define APAD 20         // 16 + 4
#define BPAD 17         // 16 + 1
#define AS_SZ (4*66*APAD)     // 5280 floats
#define BS_SZ (4*64*BPAD)     // 4352 floats
__global__ __launch_bounds__(512, 1) void conv_mma_kernel(const float* __restrict__ conv_b){
    __shared__ float sm[AS_SZ + BS_SZ];    // 38.5 KB; epilogue reuses front
    float* As = sm;
    float* Bs = sm + AS_SZ;
    int b = blockIdx.x, ytile = blockIdx.y;
    int y0 = ytile*2;
    int tid = threadIdx.x;
    int w = tid >> 5, lane = tid & 31;
    int wm = w & 3, g = w >> 2;
    int quad = lane >> 2, qk = lane & 3;
    int gtid = tid & 127;
    float* Bg = Bs + g*(64*BPAD);
    int yy = wm >> 1;
    int x0 = (wm & 1) << 5;

    float acc[2][8][4];
    #pragma unroll
    for (int i=0;i<2;i++)
        #pragma unroll
        for (int j=0;j<8;j++){ acc[i][j][0]=0.f; acc[i][j][1]=0.f; acc[i][j][2]=0.f; acc[i][j][3]=0.f; }

    const float* srcA = g_resT + (size_t)(b*PADH + y0) * (PADW*CIN);
    for (int chunk = 0; chunk < 16; chunk++){
        int c0 = chunk*CK;
        __syncthreads();
        // stage A: [r 0..3][x 0..65][k 0..15], tf32-rounded
        for (int e4 = tid; e4 < 4*66*4; e4 += 512){
            int c4 = e4 & 3;
            int xr = (e4 >> 2) % 66;
            int r  = e4 / 264;
            float4 v = *(const float4*)(srcA + ((size_t)r*PADW + xr)*CIN + c0 + c4*4);
            float* d = As + (r*66 + xr)*APAD + c4*4;
            d[0]=tf32r(v.x); d[1]=tf32r(v.y); d[2]=tf32r(v.z); d[3]=tf32r(v.w);
        }
        __syncthreads();
        for (int s = 0; s < 9; s++){
            asm volatile("bar.sync %0, 128;" :: "r"(g+1));
            // stage Bg: [n 0..63][k 0..15] from g_wr[s][c0+cc][g*64 + n]
            #pragma unroll
            for (int it = 0; it < 2; it++){
                int idx = it*128 + gtid;
                int n4 = idx & 15, cc = idx >> 4;
                float4 v = *(const float4*)(g_wr + ((size_t)(s*CIN) + c0 + cc)*CIN + g*64 + n4*4);
                Bg[(n4*4+0)*BPAD + cc] = tf32r(v.x);
                Bg[(n4*4+1)*BPAD + cc] = tf32r(v.y);
                Bg[(n4*4+2)*BPAD + cc] = tf32r(v.z);
                Bg[(n4*4+3)*BPAD + cc] = tf32r(v.w);
            }
            asm volatile("bar.sync %0, 128;" :: "r"(g+1));
            int dy = s/3, dx = s - dy*3;
            const float* Abase = As + ((yy+dy)*66 + dx)*APAD + qk;
            #pragma unroll
            for (int ks = 0; ks < 2; ks++){
                unsigned a[2][4];
                #pragma unroll
                for (int mt = 0; mt < 2; mt++){
                    const float* Ap = Abase + (x0 + mt*16 + quad)*APAD + ks*8;
                    a[mt][0] = __float_as_uint(Ap[0]);
                    a[mt][2] = __float_as_uint(Ap[4]);
                    a[mt][1] = __float_as_uint(Ap[8*APAD]);
                    a[mt][3] = __float_as_uint(Ap[8*APAD+4]);
                }
                #pragma unroll
                for (int nt = 0; nt < 8; nt++){
                    const float* Bp = Bg + (nt*8 + quad)*BPAD + ks*8 + qk;
                    unsigned b0 = __float_as_uint(Bp[0]);
                    unsigned b1 = __float_as_uint(Bp[4]);
                    mma_tf32(acc[0][nt], a[0], b0, b1);
                    mma_tf32(acc[1][nt], a[1], b0, b1);
                }
            }
        }
    }
    // epilogue: pool 2x2 + bias + relu -> g_enc
    __syncthreads();
    float* epi = sm + g*(128*BPAD);       // 2176 floats per group, 8704 total < AS_SZ+BS_SZ
    int py = ytile;
    #pragma unroll
    for (int nq = 0; nq < 4; nq++){
        #pragma unroll
        for (int mt = 0; mt < 2; mt++){
            int row0 = wm*32 + mt*16 + quad;
            #pragma unroll
            for (int j = 0; j < 2; j++){
                int nt = nq*2 + j;
                int nn = j*8 + qk*2;
                epi[ row0   *BPAD + nn]   = acc[mt][nt][0];
                epi[ row0   *BPAD + nn+1] = acc[mt][nt][1];
                epi[(row0+8)*BPAD + nn]   = acc[mt][nt][2];
                epi[(row0+8)*BPAD + nn+1] = acc[mt][nt][3];
            }
        }
        asm volatile("bar.sync %0, 128;" :: "r"(g+1));
        for (int e = gtid; e < 512; e += 128){
            int px = e >> 4, oc = e & 15;
            int m0 = px*2;
            float v = fmaxf(fmaxf(epi[ m0   *BPAD + oc], epi[(m0+1 )*BPAD + oc]),
                            fmaxf(epi[(m0+64)*BPAD + oc], epi[(m0+65)*BPAD + oc]));
            int och = g*64 + nq*16 + oc;
            g_enc[((size_t)b*LPOS + py*WF + px)*CENC + och] = fmaxf(v + conv_b[och], 0.f);
        }
        asm volatile("bar.sync %0, 128;" :: "r"(g+1));
    }
}

// ---------------- K2: positional channels ----------------
__global__ void pos_kernel(const float* __restrict__ x_emb, const float* __restrict__ y_emb){
    int idx = blockIdx.x * 256 + threadIdx.x;
    if (idx >= BATCH*LPOS*40) return;
    int c40 = idx % 40;
    int l   = (idx / 40) % LPOS;
    int b   = idx / (40*LPOS);
    int y = l / WF, xx = l % WF;
    float v = (c40 < 32) ? x_emb[xx*XOH + c40] : y_emb[y*YOH + (c40-32)];
    g_enc[((size_t)b*LPOS + l)*CENC + 256 + c40] = v;
}

// ---------------- token gather indices ----------------
__global__ void tok_kernel(const int* __restrict__ dec_t){
    int idx = blockIdx.x*256 + threadIdx.x;
    if (idx >= TLEN*BATCH) return;
    int t = idx >> 7, b = idx & 127;
    g_tok[idx] = (t == 0) ? 0 : dec_t[b*TLEN + (t-1)];
}

// ---------------- generic TN GEMM ----------------
#define BM 64
#define BN 64
#define BK 16
__global__ __launch_bounds__(256) void gemm_tn(const float* __restrict__ A, int lda,
                                               const int* __restrict__ gather,
                                               const float* __restrict__ B, int ldb,
                                               const float* __restrict__ bias,
                                               float* __restrict__ C, int ldc,
                                               int M, int N, int K){
    __shared__ __align__(16) float As[BK*68];
    __shared__ __align__(16) float Bs[BK*68];
    int m0 = blockIdx.x * BM, n0 = blockIdx.y * BN;
    int tid = threadIdx.x;
    int ty = tid >> 4, tx = tid & 15;
    float acc[4][4];
    #pragma unroll
    for (int i=0;i<4;i++) { acc[i][0]=0.f; acc[i][1]=0.f; acc[i][2]=0.f; acc[i][3]=0.f; }

    for (int k0 = 0; k0 < K; k0 += BK){
        #pragma unroll
        for (int e = tid; e < BM*BK; e += 256){
            int ml = e >> 4, kk = e & 15;
            int m = m0 + ml, k = k0 + kk;
            float v = 0.f;
            if (m < M && k < K){
                int row = gather ? gather[m] : m;
                v = A[(size_t)row*lda + k];
            }
            As[kk*68 + ml] = v;
        }
        #pragma unroll
        for (int e = tid; e < BN*BK; e += 256){
            int nl = e >> 4, kk = e & 15;
            int n = n0 + nl, k = k0 + kk;
            float v = 0.f;
            if (n < N && k < K) v = B[(size_t)n*ldb + k];
            Bs[kk*68 + nl] = v;
        }
        __syncthreads();
        #pragma unroll
        for (int kk = 0; kk < BK; kk++){
            float4 a = *(const float4*)&As[kk*68 + ty*4];
            float4 bb = *(const float4*)&Bs[kk*68 + tx*4];
            float av[4] = {a.x, a.y, a.z, a.w};
            float bv[4] = {bb.x, bb.y, bb.z, bb.w};
            #pragma unroll
            for (int i=0;i<4;i++)
                #pragma unroll
                for (int j=0;j<4;j++) acc[i][j] += av[i]*bv[j];
        }
        __syncthreads();
    }
    #pragma unroll
    for (int i=0;i<4;i++){
        int m = m0 + ty*4 + i;
        if (m >= M) continue;
        #pragma unroll
        for (int j=0;j<4;j++){
            int n = n0 + tx*4 + j;
            if (n >= N) continue;
            float bi = bias ? bias[n] : 0.f;
            C[(size_t)m*ldc + n] = acc[i][j] + bi;
        }
    }
}

// ---------------- zero hidden ----------------
__global__ void zero_hidden_kernel(){
    int idx = blockIdx.x*256 + threadIdx.x;
    if (idx < BATCH*HID) g_hidden[idx] = 0.f;
}

// ---------------- attention ----------------
__global__ __launch_bounds__(256) void attn_kernel(const float* __restrict__ attn_v_p, int t){
    int b = blockIdx.x, tid = threadIdx.x;
    __shared__ float hp[HID], vv[HID], sc[LPOS], red[256];
    hp[tid] = g_hproj[b*HID + tid];
    vv[tid] = attn_v_p[tid];
    g_rin[b*552 + tid] = g_we[((size_t)t*BATCH + b)*HID + tid];
    __syncthreads();
    int warp = tid >> 5, lane = tid & 31;
    for (int l = warp; l < LPOS; l += 8){
        const float* p = g_pre + ((size_t)b*LPOS + l)*HID;
        float s = 0.f;
        #pragma unroll
        for (int i = 0; i < 8; i++){
            int h = lane + 32*i;
            s += vv[h] * tanh_fast(p[h] + hp[h]);
        }
        s = warp_sum(s);
        if (lane == 0) sc[l] = s;
    }
    __syncthreads();
    red[tid] = sc[tid]; __syncthreads();
    for (int s = 128; s; s >>= 1){ if (tid < s) red[tid] = fmaxf(red[tid], red[tid+s]); __syncthreads(); }
    float mx = red[0]; __syncthreads();
    float e = __expf(sc[tid] - mx);
    red[tid] = e; __syncthreads();
    for (int s = 128; s; s >>= 1){ if (tid < s) red[tid] += red[tid+s]; __syncthreads(); }
    float inv = 1.f / red[0];
    __syncthreads();
    sc[tid] = e * inv;
    __syncthreads();
    const float* eb = g_enc + (size_t)b*LPOS*CENC;
    for (int c = tid; c < CENC; c += 256){
        float acc = 0.f;
        #pragma unroll 8
        for (int l = 0; l < LPOS; l++) acc += sc[l] * eb[l*CENC + c];
        g_rin[b*552 + 256 + c] = acc;
    }
}

// ---------------- GRU gates ----------------
__global__ void gates_kernel(){
    int idx = blockIdx.x*256 + threadIdx.x;
    if (idx >= BATCH*HID) return;
    int b = idx >> 8, h = idx & 255;
    const float* gi = g_gi + b*768;
    const float* gh = g_gh + b*768;
    float r = 1.f/(1.f + __expf(-(gi[h]     + gh[h])));
    float z = 1.f/(1.f + __expf(-(gi[256+h] + gh[256+h])));
    float n = tanhf(gi[512+h] + r*gh[512+h]);
    float hp = g_hidden[idx];
    g_hidden[idx] = (1.f - z)*n + z*hp;
}

// ---------------- output head ----------------
__global__ __launch_bounds__(256) void logits_kernel(const float* __restrict__ out_w,
                                                     const float* __restrict__ out_b,
                                                     const int* __restrict__ word_t, int t){
    int b = blockIdx.x, tid = threadIdx.x;
    __shared__ __align__(16) float hs[HID];
    __shared__ float lg[NC];
    __shared__ float red[256];
    hs[tid] = g_hidden[b*HID + tid];
    __syncthreads();
    float logit = -1e30f;
    if (tid < NC){
        const float4* w4 = (const float4*)(out_w + (size_t)tid*HID);
        const float4* h4 = (const float4*)hs;
        float a0=0.f, a1=0.f, a2=0.f, a3=0.f;
        #pragma unroll
        for (int k = 0; k < HID/4; k++){
            float4 w = w4[k]; float4 h = h4[k];
            a0 += w.x*h.x; a1 += w.y*h.y; a2 += w.z*h.z; a3 += w.w*h.w;
        }
        logit = (a0+a1) + (a2+a3) + out_b[tid];
        lg[tid] = logit;
    }
    red[tid] = logit; __syncthreads();
    for (int s = 128; s; s >>= 1){ if (tid < s) red[tid] = fmaxf(red[tid], red[tid+s]); __syncthreads(); }
    float mx = red[0]; __syncthreads();
    red[tid] = (tid < NC) ? __expf(lg[tid] - mx) : 0.f; __syncthreads();
    for (int s = 128; s; s >>= 1){ if (tid < s) red[tid] += red[tid+s]; __syncthreads(); }
    if (tid == 0){
        float lse = mx + logf(red[0]);
        int tgt = word_t[b*TLEN + t];
        float v = 0.f;
        if (tgt >= 0){
            int tc = tgt > (NC-1) ? (NC-1) : tgt;
            v = lse - lg[tc];
        }
        g_nll[t*BATCH + b] = v;
    }
}

// ---------------- final reduce ----------------
__global__ void reduce_kernel(float* __restrict__ out){
    __shared__ float red[256];
    int tid = threadIdx.x;
    float s = 0.f;
    for (int i = tid; i < TLEN*BATCH; i += 256) s += g_nll[i];
    red[tid] = s; __syncthreads();
    for (int k = 128; k; k >>= 1){ if (tid < k) red[tid] += red[tid+k]; __syncthreads(); }
    if (tid == 0) out[0] = 0.2f * red[0] / (float)BATCH;
}

// ---------------- host ----------------
extern "C" void kernel_launch(void* const* d_in, const int* in_sizes, int n_in,
                              void* d_out, int out_size){
    const float* x        = (const float*)d_in[0];
    const int*   dec_t    = (const int*)  d_in[1];
    const int*   word_t   = (const int*)  d_in[2];
    const float* conv_w   = (const float*)d_in[3];
    const float* conv_b   = (const float*)d_in[4];
    const float* emb_dec  = (const float*)d_in[5];
    const float* word_w   = (const float*)d_in[6];
    const float* word_b   = (const float*)d_in[7];
    const float* attn_w   = (const float*)d_in[8];
    const float* attn_b   = (const float*)d_in[9];
    const float* attn_v   = (const float*)d_in[10];
    const float* gru_wih  = (const float*)d_in[11];
    const float* gru_bih  = (const float*)d_in[12];
    const float* gru_whh  = (const float*)d_in[13];
    const float* gru_bhh  = (const float*)d_in[14];
    const float* out_w    = (const float*)d_in[15];
    const float* out_b    = (const float*)d_in[16];
    const float* x_emb    = (const float*)d_in[17];
    const float* y_emb    = (const float*)d_in[18];
    float* out = (float*)d_out;

    float *p_rin = nullptr, *p_hid = nullptr, *p_hpj = nullptr, *p_gi = nullptr, *p_gh = nullptr;
    float *p_enc = nullptr, *p_pre = nullptr, *p_we = nullptr;
    int   *p_tok = nullptr;
    cudaGetSymbolAddress((void**)&p_rin, g_rin);
    cudaGetSymbolAddress((void**)&p_hid, g_hidden);
    cudaGetSymbolAddress((void**)&p_hpj, g_hproj);
    cudaGetSymbolAddress((void**)&p_gi,  g_gi);
    cudaGetSymbolAddress((void**)&p_gh,  g_gh);
    cudaGetSymbolAddress((void**)&p_enc, g_enc);
    cudaGetSymbolAddress((void**)&p_pre, g_pre);
    cudaGetSymbolAddress((void**)&p_we,  g_we);
    cudaGetSymbolAddress((void**)&p_tok, g_tok);

    // 1) resize to channel-last padded + weight reorg
    {
        int n = BATCH*PADH*PADW*CIN;
        resize_cl_kernel<<<(n + 255)/256, 256>>>(x);
    }
    wreorg_kernel<<<(9*CIN*CIN + 255)/256, 256>>>(conv_w);
    // 2) conv as tensor-core GEMM + pool + relu
    conv_mma_kernel<<<dim3(BATCH, 8), 512>>>(conv_b);
    // 3) positional channels
    {
        int n = BATCH*LPOS*40;
        pos_kernel<<<(n + 255)/256, 256>>>(x_emb, y_emb);
    }
    // 4) teacher-forcing tokens + batched word embedding GEMM
    tok_kernel<<<(TLEN*BATCH + 255)/256, 256>>>(dec_t);
    gemm_tn<<<dim3((TLEN*BATCH)/BM, HID/BN), 256>>>(
        emb_dec, NC, p_tok, word_w, NC, word_b, p_we, HID, TLEN*BATCH, HID, NC);
    // 5) enc pre-projection
    gemm_tn<<<dim3((BATCH*LPOS)/BM, HID/BN), 256>>>(
        p_enc, CENC, nullptr, attn_w + 256, 2*HID + XOH + YOH, attn_b,
        p_pre, HID, BATCH*LPOS, HID, CENC);
    // 6) init hidden
    zero_hidden_kernel<<<(BATCH*HID + 255)/256, 256>>>();

    // 7) sequential decoder
    for (int t = 0; t < TLEN; t++){
        gemm_tn<<<dim3(BATCH/BM, HID/BN), 256>>>(
            p_hid, HID, nullptr, attn_w, 2*HID + XOH + YOH, nullptr,
            p_hpj, HID, BATCH, HID, HID);
        attn_kernel<<<BATCH, 256>>>(attn_v, t);
        gemm_tn<<<dim3(BATCH/BM, (3*HID)/BN), 256>>>(
            p_rin, 552, nullptr, gru_wih, 552, gru_bih, p_gi, 3*HID, BATCH, 3*HID, 552);
        gemm_tn<<<dim3(BATCH/BM, (3*HID)/BN), 256>>>(
            p_hid, HID, nullptr, gru_whh, HID, gru_bhh, p_gh, 3*HID, BATCH, 3*HID, HID);
        gates_kernel<<<(BATCH*HID + 255)/256, 256>>>();
        logits_kernel<<<BATCH, 256>>>(out_w, out_b, word_t, t);
    }
    // 8) loss
    reduce_kernel<<<1, 256>>>(out);
    (void)in_sizes; (void)n_in; (void)out_size;
}

// round 3
// speedup vs baseline: 1.6591x; 1.1893x over previous
#include <cuda_runtime.h>
#include <cuda_bf16.h>
#include <math.h>

// ---------------- Problem constants ----------------
#define BATCH   128
#define CIN     256
#define HIN     8
#define WIN     32
#define RH      16
#define RW      64
#define HF      8
#define WF      32
#define LPOS    256
#define XOH     32
#define YOH     8
#define CENC    296
#define HID     256
#define NC      163
#define TLEN    32

#define PADH    18
#define PADW    66

// ---------------- Scratch ----------------
__device__ float g_resT[BATCH*PADH*PADW*CIN];
__device__ float g_wr  [9*CIN*CIN];
__device__ float g_enc[BATCH*LPOS*CENC];
__device__ float g_pre[BATCH*LPOS*HID];
__device__ float g_we [TLEN*BATCH*HID];
__device__ float g_giw[TLEN*768*BATCH];           // [t][j][b]
__device__ int   g_tok[TLEN*BATCH];
__device__ float g_hT   [HID*BATCH];              // [k][b]
__device__ float g_hcatT[1024*BATCH];             // [j][b]: 0:256 hproj, 256:1024 gh
__device__ float g_ctxT [CENC*BATCH];             // [c][b]
__device__ float g_owT  [HID*NC];                 // [k][j]
__device__ float g_nll  [TLEN*BATCH];
__device__ unsigned g_bar_arrive;
__device__ unsigned g_bar_epoch;

// ---------------- helpers ----------------
__device__ __forceinline__ float tanh_fast(float x){
    float y; asm("tanh.approx.f32 %0, %1;" : "=f"(y) : "f"(x)); return y;
}
__device__ __forceinline__ float warp_sum(float v){
    #pragma unroll
    for (int o = 16; o; o >>= 1) v += __shfl_down_sync(0xffffffffu, v, o);
    return v;
}
__device__ __forceinline__ float tf32r(float f){
    unsigned u; asm("cvt.rna.tf32.f32 %0, %1;" : "=r"(u) : "f"(f));
    return __uint_as_float(u);
}
__device__ __forceinline__ void mma_tf32(float* c, const unsigned* a, unsigned b0, unsigned b1){
    asm volatile("mma.sync.aligned.m16n8k8.row.col.f32.tf32.tf32.f32 "
        "{%0,%1,%2,%3}, {%4,%5,%6,%7}, {%8,%9}, {%0,%1,%2,%3};"
        : "+f"(c[0]), "+f"(c[1]), "+f"(c[2]), "+f"(c[3])
        : "r"(a[0]), "r"(a[1]), "r"(a[2]), "r"(a[3]), "r"(b0), "r"(b1));
}
__device__ __forceinline__ unsigned ld_acq(unsigned* p){
    unsigned v; asm volatile("ld.acquire.gpu.u32 %0, [%1];" : "=r"(v) : "l"(p)); return v;
}
__device__ __forceinline__ void grid_barrier(unsigned target){
    __syncthreads();
    if (threadIdx.x == 0){
        __threadfence();
        unsigned t = atomicAdd(&g_bar_arrive, 1u);
        if (t == gridDim.x - 1){
            g_bar_arrive = 0u;
            asm volatile("red.release.gpu.add.u32 [%0], 1;" :: "l"(&g_bar_epoch));
        } else {
            while ((int)(ld_acq(&g_bar_epoch) - target) < 0) { }
        }
    }
    __syncthreads();
}

// ---------------- K0: bilinear 2x resize -> channel-last padded ----------------
__global__ void resize_cl_kernel(const float* __restrict__ x){
    int idx = blockIdx.x * 256 + threadIdx.x;
    if (idx >= BATCH*PADH*PADW*CIN) return;
    int c  = idx & 255;
    int t  = idx >> 8;
    int xp = t % PADW;  t /= PADW;
    int yp = t % PADH;
    int b  = t / PADH;
    float v = 0.f;
    if (xp >= 1 && xp < PADW-1 && yp >= 1 && yp < PADH-1){
        int yo = yp - 1, xo = xp - 1;
        float sy = 0.5f*yo - 0.25f;
        int y0 = (int)floorf(sy); float fy = sy - (float)y0;
        int y0c = y0 < 0 ? 0 : y0;
        int y1c = (y0+1) > (HIN-1) ? (HIN-1) : (y0+1);
        float sx = 0.5f*xo - 0.25f;
        int x0 = (int)floorf(sx); float fx = sx - (float)x0;
        int x0c = x0 < 0 ? 0 : x0;
        int x1c = (x0+1) > (WIN-1) ? (WIN-1) : (x0+1);
        const float* base = x + (size_t)(b*CIN + c) * (HIN*WIN);
        float v00 = base[y0c*WIN + x0c], v01 = base[y0c*WIN + x1c];
        float v10 = base[y1c*WIN + x0c], v11 = base[y1c*WIN + x1c];
        v = (1.f-fy)*((1.f-fx)*v00 + fx*v01) + fy*((1.f-fx)*v10 + fx*v11);
    }
    g_resT[idx] = v;
}

// ---------------- K0b: weight reorg ----------------
__global__ void wreorg_kernel(const float* __restrict__ conv_w){
    int idx = blockIdx.x*256 + threadIdx.x;
    if (idx >= 9*CIN*CIN) return;
    int o = idx & 255;
    int c = (idx >> 8) & 255;
    int s = idx >> 16;
    g_wr[idx] = conv_w[(o*CIN + c)*9 + s];
}

// ---------------- K0c: out_w transpose ----------------
__global__ void owt_kernel(const float* __restrict__ out_w){
    int idx = blockIdx.x*256 + threadIdx.x;
    if (idx >= NC*HID) return;
    int j = idx >> 8, k = idx & 255;
    g_owT[k*NC + j] = out_w[idx];
}

// ---------------- K1: conv3x3 as 9-shift tf32 MMA + pool + relu ----------------
#define APAD 20
#define BPAD 17
#define AS_SZ (4*66*APAD)
#define BS_SZ (4*64*BPAD)
__global__ __launch_bounds__(512, 1) void conv_mma_kernel(const float* __restrict__ conv_b){
    __shared__ float sm[AS_SZ + BS_SZ];
    float* As = sm;
    float* Bs = sm + AS_SZ;
    int b = blockIdx.x, ytile = blockIdx.y;
    int y0 = ytile*2;
    int tid = threadIdx.x;
    int w = tid >> 5, lane = tid & 31;
    int wm = w & 3, g = w >> 2;
    int quad = lane >> 2, qk = lane & 3;
    int gtid = tid & 127;
    float* Bg = Bs + g*(64*BPAD);
    int yy = wm >> 1;
    int x0 = (wm & 1) << 5;

    float acc[2][8][4];
    #pragma unroll
    for (int i=0;i<2;i++)
        #pragma unroll
        for (int j=0;j<8;j++){ acc[i][j][0]=0.f; acc[i][j][1]=0.f; acc[i][j][2]=0.f; acc[i][j][3]=0.f; }

    const float* srcA = g_resT + (size_t)(b*PADH + y0) * (PADW*CIN);
    for (int chunk = 0; chunk < 16; chunk++){
        int c0 = chunk*16;
        __syncthreads();
        for (int e4 = tid; e4 < 4*66*4; e4 += 512){
            int c4 = e4 & 3;
            int xr = (e4 >> 2) % 66;
            int r  = e4 / 264;
            float4 v = *(const float4*)(srcA + ((size_t)r*PADW + xr)*CIN + c0 + c4*4);
            float* d = As + (r*66 + xr)*APAD + c4*4;
            d[0]=tf32r(v.x); d[1]=tf32r(v.y); d[2]=tf32r(v.z); d[3]=tf32r(v.w);
        }
        __syncthreads();
        for (int s = 0; s < 9; s++){
            asm volatile("bar.sync %0, 128;" :: "r"(g+1));
            #pragma unroll
            for (int it = 0; it < 2; it++){
                int idx = it*128 + gtid;
                int n4 = idx & 15, cc = idx >> 4;
                float4 v = *(const float4*)(g_wr + ((size_t)(s*CIN) + c0 + cc)*CIN + g*64 + n4*4);
                Bg[(n4*4+0)*BPAD + cc] = tf32r(v.x);
                Bg[(n4*4+1)*BPAD + cc] = tf32r(v.y);
                Bg[(n4*4+2)*BPAD + cc] = tf32r(v.z);
                Bg[(n4*4+3)*BPAD + cc] = tf32r(v.w);
            }
            asm volatile("bar.sync %0, 128;" :: "r"(g+1));
            int dy = s/3, dx = s - dy*3;
            const float* Abase = As + ((yy+dy)*66 + dx)*APAD + qk;
            #pragma unroll
            for (int ks = 0; ks < 2; ks++){
                unsigned a[2][4];
                #pragma unroll
                for (int mt = 0; mt < 2; mt++){
                    const float* Ap = Abase + (x0 + mt*16 + quad)*APAD + ks*8;
                    a[mt][0] = __float_as_uint(Ap[0]);
                    a[mt][2] = __float_as_uint(Ap[4]);
                    a[mt][1] = __float_as_uint(Ap[8*APAD]);
                    a[mt][3] = __float_as_uint(Ap[8*APAD+4]);
                }
                #pragma unroll
                for (int nt = 0; nt < 8; nt++){
                    const float* Bp = Bg + (nt*8 + quad)*BPAD + ks*8 + qk;
                    unsigned b0 = __float_as_uint(Bp[0]);
                    unsigned b1 = __float_as_uint(Bp[4]);
                    mma_tf32(acc[0][nt], a[0], b0, b1);
                    mma_tf32(acc[1][nt], a[1], b0, b1);
                }
            }
        }
    }
    __syncthreads();
    float* epi = sm + g*(128*BPAD);
    int py = ytile;
    #pragma unroll
    for (int nq = 0; nq < 4; nq++){
        #pragma unroll
        for (int mt = 0; mt < 2; mt++){
            int row0 = wm*32 + mt*16 + quad;
            #pragma unroll
            for (int j = 0; j < 2; j++){
                int nt = nq*2 + j;
                int nn = j*8 + qk*2;
                epi[ row0   *BPAD + nn]   = acc[mt][nt][0];
                epi[ row0   *BPAD + nn+1] = acc[mt][nt][1];
                epi[(row0+8)*BPAD + nn]   = acc[mt][nt][2];
                epi[(row0+8)*BPAD + nn+1] = acc[mt][nt][3];
            }
        }
        asm volatile("bar.sync %0, 128;" :: "r"(g+1));
        for (int e = gtid; e < 512; e += 128){
            int px = e >> 4, oc = e & 15;
            int m0 = px*2;
            float v = fmaxf(fmaxf(epi[ m0   *BPAD + oc], epi[(m0+1 )*BPAD + oc]),
                            fmaxf(epi[(m0+64)*BPAD + oc], epi[(m0+65)*BPAD + oc]));
            int och = g*64 + nq*16 + oc;
            g_enc[((size_t)b*LPOS + py*WF + px)*CENC + och] = fmaxf(v + conv_b[och], 0.f);
        }
        asm volatile("bar.sync %0, 128;" :: "r"(g+1));
    }
}

// ---------------- K2: positional channels ----------------
__global__ void pos_kernel(const float* __restrict__ x_emb, const float* __restrict__ y_emb){
    int idx = blockIdx.x * 256 + threadIdx.x;
    if (idx >= BATCH*LPOS*40) return;
    int c40 = idx % 40;
    int l   = (idx / 40) % LPOS;
    int b   = idx / (40*LPOS);
    int y = l / WF, xx = l % WF;
    float v = (c40 < 32) ? x_emb[xx*XOH + c40] : y_emb[y*YOH + (c40-32)];
    g_enc[((size_t)b*LPOS + l)*CENC + 256 + c40] = v;
}

// ---------------- token gather ----------------
__global__ void tok_kernel(const int* __restrict__ dec_t){
    int idx = blockIdx.x*256 + threadIdx.x;
    if (idx >= TLEN*BATCH) return;
    int t = idx >> 7, b = idx & 127;
    g_tok[idx] = (t == 0) ? 0 : dec_t[b*TLEN + (t-1)];
}

// ---------------- generic TN GEMM (tmode=1: store C[((m>>7)*N+n)*128 + (m&127)]) ----------------
#define BM 64
#define BN 64
#define BK 16
__global__ __launch_bounds__(256) void gemm_tn(const float* __restrict__ A, int lda,
                                               const int* __restrict__ gather,
                                               const float* __restrict__ B, int ldb,
                                               const float* __restrict__ bias,
                                               float* __restrict__ C, int ldc,
                                               int M, int N, int K, int tmode){
    __shared__ __align__(16) float As[BK*68];
    __shared__ __align__(16) float Bs[BK*68];
    int m0 = blockIdx.x * BM, n0 = blockIdx.y * BN;
    int tid = threadIdx.x;
    int ty = tid >> 4, tx = tid & 15;
    float acc[4][4];
    #pragma unroll
    for (int i=0;i<4;i++) { acc[i][0]=0.f; acc[i][1]=0.f; acc[i][2]=0.f; acc[i][3]=0.f; }

    for (int k0 = 0; k0 < K; k0 += BK){
        #pragma unroll
        for (int e = tid; e < BM*BK; e += 256){
            int ml = e >> 4, kk = e & 15;
            int m = m0 + ml, k = k0 + kk;
            float v = 0.f;
            if (m < M && k < K){
                int row = gather ? gather[m] : m;
                v = A[(size_t)row*lda + k];
            }
            As[kk*68 + ml] = v;
        }
        #pragma unroll
        for (int e = tid; e < BN*BK; e += 256){
            int nl = e >> 4, kk = e & 15;
            int n = n0 + nl, k = k0 + kk;
            float v = 0.f;
            if (n < N && k < K) v = B[(size_t)n*ldb + k];
            Bs[kk*68 + nl] = v;
        }
        __syncthreads();
        #pragma unroll
        for (int kk = 0; kk < BK; kk++){
            float4 a = *(const float4*)&As[kk*68 + ty*4];
            float4 bb = *(const float4*)&Bs[kk*68 + tx*4];
            float av[4] = {a.x, a.y, a.z, a.w};
            float bv[4] = {bb.x, bb.y, bb.z, bb.w};
            #pragma unroll
            for (int i=0;i<4;i++)
                #pragma unroll
                for (int j=0;j<4;j++) acc[i][j] += av[i]*bv[j];
        }
        __syncthreads();
    }
    #pragma unroll
    for (int i=0;i<4;i++){
        int m = m0 + ty*4 + i;
        if (m >= M) continue;
        #pragma unroll
        for (int j=0;j<4;j++){
            int n = n0 + tx*4 + j;
            if (n >= N) continue;
            float bi = bias ? bias[n] : 0.f;
            if (tmode == 0) C[(size_t)m*ldc + n] = acc[i][j] + bi;
            else            C[((size_t)(m>>7)*N + n)*128 + (m&127)] = acc[i][j] + bi;
        }
    }
}

// ---------------- persistent decoder ----------------
__global__ __launch_bounds__(256) void decoder_kernel(
    const float* __restrict__ attn_v, const float* __restrict__ attn_w,
    const float* __restrict__ whh, const float* __restrict__ bhh,
    const float* __restrict__ wih, const float* __restrict__ out_b,
    const int* __restrict__ word_t, float* __restrict__ out)
{
    __shared__ float sm[8192];
    __shared__ unsigned ep0s;
    int cta = blockIdx.x, tid = threadIdx.x;
    int b127 = tid & 127, half = tid >> 7;

    g_hT[cta*256 + tid] = 0.f;
    if (tid == 0) ep0s = ld_acq(&g_bar_epoch);
    __syncthreads();
    unsigned bt = ep0s;
    grid_barrier(++bt);

    for (int it = 0; it <= TLEN; it++){
        // ---- P1: hcatT rows [cta*8, cta*8+8): [hproj | gh] ----
        if (it < TLEN){
            int jj0 = cta*8;
            float* Wb = sm;            // 2048
            float* bias = sm + 2048;   // 8
            float* hs = sm + 2176;     // 4096
            #pragma unroll
            for (int i = 0; i < 8; i++){
                int idx = i*256 + tid;
                int row = idx >> 8, k = idx & 255;
                int j = jj0 + row;
                Wb[idx] = (j < 256) ? attn_w[j*552 + k] : whh[(j-256)*256 + k];
            }
            if (tid < 8){
                int j = jj0 + tid;
                bias[tid] = (j < 256) ? 0.f : bhh[j-256];
            }
            float a0=0.f, a1=0.f, a2=0.f, a3=0.f;
            for (int kc = 0; kc < 8; kc++){
                __syncthreads();
                #pragma unroll
                for (int i = 0; i < 16; i++){
                    int idx = i*256 + tid;
                    hs[idx] = g_hT[kc*4096 + idx];
                }
                __syncthreads();
                #pragma unroll
                for (int kk = 0; kk < 32; kk++){
                    float hv = hs[kk*128 + b127];
                    int k = kc*32 + kk;
                    a0 += Wb[(half+0)*256 + k]*hv;
                    a1 += Wb[(half+2)*256 + k]*hv;
                    a2 += Wb[(half+4)*256 + k]*hv;
                    a3 += Wb[(half+6)*256 + k]*hv;
                }
            }
            g_hcatT[(jj0 + half+0)*128 + b127] = a0 + bias[half+0];
            g_hcatT[(jj0 + half+2)*128 + b127] = a1 + bias[half+2];
            g_hcatT[(jj0 + half+4)*128 + b127] = a2 + bias[half+4];
            g_hcatT[(jj0 + half+6)*128 + b127] = a3 + bias[half+6];
        }
        // ---- P4 (logits of previous step, uses current h) ----
        if (it > 0){
            int b = cta;
            float* hsd = sm;          // 256
            float* lg  = sm + 256;    // 163
            float* red = sm + 512;    // 256
            __syncthreads();
            hsd[tid] = g_hT[tid*128 + b];
            __syncthreads();
            float logit = -1e30f;
            if (tid < NC){
                float a = 0.f;
                #pragma unroll 8
                for (int k = 0; k < HID; k++) a += g_owT[k*NC + tid]*hsd[k];
                logit = a + out_b[tid];
                lg[tid] = logit;
            }
            red[tid] = logit; __syncthreads();
            for (int s = 128; s; s >>= 1){ if (tid < s) red[tid] = fmaxf(red[tid], red[tid+s]); __syncthreads(); }
            float mx = red[0]; __syncthreads();
            red[tid] = (tid < NC) ? __expf(lg[tid] - mx) : 0.f; __syncthreads();
            for (int s = 128; s; s >>= 1){ if (tid < s) red[tid] += red[tid+s]; __syncthreads(); }
            if (tid == 0){
                float lse = mx + logf(red[0]);
                int tgt = word_t[b*TLEN + (it-1)];
                float v = 0.f;
                if (tgt >= 0){
                    int tc = tgt > (NC-1) ? (NC-1) : tgt;
                    v = lse - lg[tc];
                }
                g_nll[(it-1)*BATCH + b] = v;
            }
        }
        grid_barrier(++bt);
        if (it == TLEN) break;

        // ---- P2: attention for b = cta ----
        {
            int b = cta;
            float* vv = sm;          // 256
            float* hp = sm + 256;    // 256
            float* sc = sm + 512;    // 256
            float* red = sm + 768;   // 256
            vv[tid] = attn_v[tid];
            hp[tid] = g_hcatT[tid*128 + b];
            __syncthreads();
            int warp = tid >> 5, lane = tid & 31;
            for (int l = warp; l < LPOS; l += 8){
                const float* p = g_pre + ((size_t)b*LPOS + l)*HID;
                float s = 0.f;
                #pragma unroll
                for (int i = 0; i < 8; i++){
                    int h = lane + 32*i;
                    s += vv[h] * tanh_fast(p[h] + hp[h]);
                }
                s = warp_sum(s);
                if (lane == 0) sc[l] = s;
            }
            __syncthreads();
            red[tid] = sc[tid]; __syncthreads();
            for (int s = 128; s; s >>= 1){ if (tid < s) red[tid] = fmaxf(red[tid], red[tid+s]); __syncthreads(); }
            float mx = red[0]; __syncthreads();
            float e = __expf(sc[tid] - mx);
            red[tid] = e; __syncthreads();
            for (int s = 128; s; s >>= 1){ if (tid < s) red[tid] += red[tid+s]; __syncthreads(); }
            float inv = 1.f / red[0];
            __syncthreads();
            sc[tid] = e * inv;
            __syncthreads();
            const float* eb = g_enc + (size_t)b*LPOS*CENC;
            float acc1 = 0.f, acc2 = 0.f;
            #pragma unroll 4
            for (int l = 0; l < LPOS; l++){
                float wl = sc[l];
                acc1 += wl * eb[l*CENC + tid];
                if (tid < 40) acc2 += wl * eb[l*CENC + 256 + tid];
            }
            g_ctxT[tid*128 + b] = acc1;
            if (tid < 40) g_ctxT[(256+tid)*128 + b] = acc2;
        }
        grid_barrier(++bt);

        // ---- P3: gi_ctx + gates for hh = cta*2 + half ----
        {
            int hh0 = cta*2;
            float* Ws = sm;           // 1776
            float* cs = sm + 1792;    // up to 6144
            for (int idx = tid; idx < 6*CENC; idx += 256){
                int r = idx / CENC, c = idx - r*CENC;
                int rhalf = r / 3, gate = r - rhalf*3;
                int j = gate*256 + hh0 + rhalf;
                Ws[idx] = wih[j*552 + 256 + c];
            }
            float ar = 0.f, az = 0.f, an = 0.f;
            int hh = hh0 + half;
            for (int c0 = 0; c0 < CENC; c0 += 48){
                int len = (CENC - c0) < 48 ? (CENC - c0) : 48;
                __syncthreads();
                for (int idx = tid; idx < len*128; idx += 256)
                    cs[idx] = g_ctxT[c0*128 + idx];
                __syncthreads();
                for (int cc = 0; cc < len; cc++){
                    float cv = cs[cc*128 + b127];
                    int c = c0 + cc;
                    ar += Ws[(half*3+0)*CENC + c]*cv;
                    az += Ws[(half*3+1)*CENC + c]*cv;
                    an += Ws[(half*3+2)*CENC + c]*cv;
                }
            }
            const float* giw = g_giw + (size_t)it*768*128;
            float gir = giw[(      hh)*128 + b127] + ar;
            float giz = giw[(256 + hh)*128 + b127] + az;
            float gin = giw[(512 + hh)*128 + b127] + an;
            float ghr = g_hcatT[(256 +       hh)*128 + b127];
            float ghz = g_hcatT[(256 + 256 + hh)*128 + b127];
            float ghn = g_hcatT[(256 + 512 + hh)*128 + b127];
            float r = 1.f/(1.f + __expf(-(gir + ghr)));
            float z = 1.f/(1.f + __expf(-(giz + ghz)));
            float n = tanhf(gin + r*ghn);
            float ho = g_hT[hh*128 + b127];
            g_hT[hh*128 + b127] = (1.f - z)*n + z*ho;
        }
        grid_barrier(++bt);
    }

    // ---- final reduce (CTA 0) ----
    if (cta == 0){
        float* red = sm;
        float s = 0.f;
        for (int i = tid; i < TLEN*BATCH; i += 256) s += g_nll[i];
        red[tid] = s; __syncthreads();
        for (int k = 128; k; k >>= 1){ if (tid < k) red[tid] += red[tid+k]; __syncthreads(); }
        if (tid == 0) out[0] = 0.2f * red[0] / (float)BATCH;
    }
}

// ---------------- host ----------------
extern "C" void kernel_launch(void* const* d_in, const int* in_sizes, int n_in,
                              void* d_out, int out_size){
    const float* x        = (const float*)d_in[0];
    const int*   dec_t    = (const int*)  d_in[1];
    const int*   word_t   = (const int*)  d_in[2];
    const float* conv_w   = (const float*)d_in[3];
    const float* conv_b   = (const float*)d_in[4];
    const float* emb_dec  = (const float*)d_in[5];
    const float* word_w   = (const float*)d_in[6];
    const float* word_b   = (const float*)d_in[7];
    const float* attn_w   = (const float*)d_in[8];
    const float* attn_b   = (const float*)d_in[9];
    const float* attn_v   = (const float*)d_in[10];
    const float* gru_wih  = (const float*)d_in[11];
    const float* gru_bih  = (const float*)d_in[12];
    const float* gru_whh  = (const float*)d_in[13];
    const float* gru_bhh  = (const float*)d_in[14];
    const float* out_w    = (const float*)d_in[15];
    const float* out_b    = (const float*)d_in[16];
    const float* x_emb    = (const float*)d_in[17];
    const float* y_emb    = (const float*)d_in[18];
    float* out = (float*)d_out;

    float *p_enc = nullptr, *p_pre = nullptr, *p_we = nullptr, *p_giw = nullptr;
    int   *p_tok = nullptr;
    cudaGetSymbolAddress((void**)&p_enc, g_enc);
    cudaGetSymbolAddress((void**)&p_pre, g_pre);
    cudaGetSymbolAddress((void**)&p_we,  g_we);
    cudaGetSymbolAddress((void**)&p_giw, g_giw);
    cudaGetSymbolAddress((void**)&p_tok, g_tok);

    {
        int n = BATCH*PADH*PADW*CIN;
        resize_cl_kernel<<<(n + 255)/256, 256>>>(x);
    }
    wreorg_kernel<<<(9*CIN*CIN + 255)/256, 256>>>(conv_w);
    owt_kernel<<<(NC*HID + 255)/256, 256>>>(out_w);
    conv_mma_kernel<<<dim3(BATCH, 8), 512>>>(conv_b);
    {
        int n = BATCH*LPOS*40;
        pos_kernel<<<(n + 255)/256, 256>>>(x_emb, y_emb);
    }
    tok_kernel<<<(TLEN*BATCH + 255)/256, 256>>>(dec_t);
    // we = emb[tok] @ word_w^T + word_b
    gemm_tn<<<dim3((TLEN*BATCH)/BM, HID/BN), 256>>>(
        emb_dec, NC, p_tok, word_w, NC, word_b, p_we, HID, TLEN*BATCH, HID, NC, 0);
    // gi_weT[t][j][b] = we @ wih[:, :256]^T + bih
    gemm_tn<<<dim3((TLEN*BATCH)/BM, (3*HID)/BN), 256>>>(
        p_we, HID, nullptr, gru_wih, 552, gru_bih, p_giw, 0, TLEN*BATCH, 3*HID, HID, 1);
    // pre = enc @ We^T + attn_b
    gemm_tn<<<dim3((BATCH*LPOS)/BM, HID/BN), 256>>>(
        p_enc, CENC, nullptr, attn_w + 256, 552, attn_b, p_pre, HID, BATCH*LPOS, HID, CENC, 0);
    // persistent decoder (all 32 steps + final loss)
    decoder_kernel<<<BATCH, 256>>>(attn_v, attn_w, gru_whh, gru_bhh, gru_wih,
                                   out_b, word_t, out);
    (void)in_sizes; (void)n_in; (void)out_size;
}